// round 17
// baseline (speedup 1.0000x reference)
#include <cuda_runtime.h>
#include <math.h>

// B=8, D=64, O=256, I=256, G=128
// Output: V(8) | A(8*65536) | hn(8*64) | cn(8*64)
#define OFF_V  0
#define OFF_A  8
#define OFF_HN 524296
#define OFF_CN 524808

// ---- scratch ----
__device__ float g_hn[8 * 64];
__device__ float g_M2[128 * 64];        // Wa1@Ws
__device__ float g_bba[128];            // Wa1@ba0 + ba1
__device__ float g_c1[128];
__device__ float g_c2d[256];
__device__ float g_vvT[8 * 128 * 256];  // [b][g][o]  (raw, no u)
__device__ float g_wT[8 * 128 * 256];   // [b][g][i]

__device__ __forceinline__ float sigm(float x) { return 1.0f / (1.0f + expf(-x)); }

__device__ __forceinline__ float warp_sum(float v) {
    #pragma unroll
    for (int o = 16; o; o >>= 1) v += __shfl_xor_sync(0xffffffffu, v, o);
    return v;
}

__device__ __forceinline__ unsigned long long addp(unsigned long long a, unsigned long long b) {
    unsigned long long r;
    asm("add.rn.f32x2 %0, %1, %2;" : "=l"(r) : "l"(a), "l"(b));
    return r;
}
__device__ __forceinline__ unsigned long long fmap(unsigned long long a, unsigned long long b, unsigned long long c) {
    unsigned long long r;
    asm("fma.rn.f32x2 %0, %1, %2, %3;" : "=l"(r) : "l"(a), "l"(b), "l"(c));
    return r;
}
__device__ __forceinline__ float plo(unsigned long long p) {
    return __uint_as_float((unsigned)(p & 0xffffffffULL));
}
__device__ __forceinline__ float phi(unsigned long long p) {
    return __uint_as_float((unsigned)(p >> 32));
}

// ============================================================
// KA (producer), 145 blocks x 256 thr, dsm 69888 B. (unchanged)
// ============================================================
__global__ void __launch_bounds__(256) k_prod(
        const float* __restrict__ ope,  const float* __restrict__ ins,
        const float* __restrict__ h_in, const float* __restrict__ c_in,
        const float* __restrict__ W_ih, const float* __restrict__ W_hh,
        const float* __restrict__ b_ih, const float* __restrict__ b_hh,
        const float* __restrict__ Wa0,  const float* __restrict__ ba0,
        const float* __restrict__ Wa1,  const float* __restrict__ ba1,
        const float* __restrict__ Wa2,
        float* __restrict__ out)
{
    extern __shared__ float dsm[];
    const int bid = blockIdx.x;
    const int t = threadIdx.x;

    if (bid < 128 || (bid >= 136 && bid < 144)) {
        const bool isM2 = (bid >= 136);
        const int m  = isM2 ? 2 : (bid >> 6);
        const int b  = isM2 ? 0 : ((bid >> 3) & 7);
        const int gc = isM2 ? (bid - 136) : (bid & 7);

        float* sA = dsm;              // 16*129
        float* sB = dsm + 2064;       // 128*72
        float* sM = dsm + 16384;      // 16*68
        float* sIn = dsm;             // [0..16384) after GEMM

        #pragma unroll
        for (int i = 0; i < 8; i++) {
            int idx = t + i * 256;
            sA[(idx >> 7) * 129 + (idx & 127)] = Wa1[gc * 2048 + idx];
        }
        const int coff = (m == 2) ? 0 : (64 + m * 64);
        {
            int hh0 = t >> 4, c4 = t & 15;
            #pragma unroll
            for (int i = 0; i < 8; i++) {
                int hh = hh0 + i * 16;
                float4 v = *(const float4*)(Wa0 + hh * 192 + coff + c4 * 4);
                *(float4*)(sB + hh * 72 + c4 * 4) = v;
            }
        }
        __syncthreads();

        {
            const int g = t >> 4, dg = t & 15;
            float4 acc = make_float4(0.f, 0.f, 0.f, 0.f);
            const float* ar = sA + g * 129;
            const float* bc = sB + dg * 4;
            #pragma unroll 8
            for (int hh = 0; hh < 128; hh++) {
                float a = ar[hh];
                float4 bv = *(const float4*)(bc + hh * 72);
                acc.x += a * bv.x; acc.y += a * bv.y; acc.z += a * bv.z; acc.w += a * bv.w;
            }
            *(float4*)(sM + g * 68 + dg * 4) = acc;
        }
        __syncthreads();

        if (isM2) {
            const int g = t >> 4, dg = t & 15;
            *(float4*)(g_M2 + (gc * 16 + g) * 64 + dg * 4) =
                *(const float4*)(sM + g * 68 + dg * 4);
            return;
        }

        const int g = t & 15, xg = t >> 4;
        unsigned long long mu[32];
        #pragma unroll
        for (int j = 0; j < 16; j++) {
            ulonglong2 p = *(const ulonglong2*)(sM + g * 68 + 4 * j);
            mu[2 * j] = p.x; mu[2 * j + 1] = p.y;
        }

        const float* src = (m == 0) ? (ope + (b * 258 + 1) * 64)
                                    : (ins + b * 256 * 64);
        {
            const float4* g4 = (const float4*)src;
            #pragma unroll
            for (int k = 0; k < 16; k++)
                ((float4*)sIn)[t + k * 256] = g4[t + k * 256];
        }
        __syncthreads();

        float accs[16];
        #pragma unroll 4
        for (int rr = 0; rr < 16; rr++) {
            int row = (rr >> 3) * 128 + xg * 8 + (rr & 7);
            const ulonglong2* ip = (const ulonglong2*)(sIn + row * 64);
            unsigned long long a0 = 0ULL, a1 = 0ULL;
            #pragma unroll
            for (int j = 0; j < 16; j++) {
                ulonglong2 xx = ip[j];
                a0 = fmap(mu[2 * j], xx.x, a0);
                a1 = fmap(mu[2 * j + 1], xx.y, a1);
            }
            accs[rr] = plo(a0) + phi(a0) + plo(a1) + phi(a1);
        }

        float* dst = ((m == 0) ? g_vvT : g_wT) + b * 32768 + (gc * 16 + g) * 256 + xg * 8;
        *(float4*)(dst)           = make_float4(accs[0],  accs[1],  accs[2],  accs[3]);
        *(float4*)(dst + 4)       = make_float4(accs[4],  accs[5],  accs[6],  accs[7]);
        *(float4*)(dst + 128)     = make_float4(accs[8],  accs[9],  accs[10], accs[11]);
        *(float4*)(dst + 132)     = make_float4(accs[12], accs[13], accs[14], accs[15]);
        return;
    }

    if (bid == 144) {
        __shared__ float sb[128];
        if (t < 128) sb[t] = ba0[t];
        __syncthreads();
        if (t < 128) {
            float acc = ba1[t];
            const float4* row = (const float4*)(Wa1 + t * 128);
            #pragma unroll 8
            for (int j = 0; j < 32; j++) {
                float4 w4 = row[j];
                float4 x4 = *(const float4*)(sb + j * 4);
                acc += w4.x * x4.x + w4.y * x4.y + w4.z * x4.z + w4.w * x4.w;
            }
            g_bba[t] = acc;
            float w2 = Wa2[t];
            g_c1[t] = 0.505f * w2;
            g_c2d[2 * t]     = 0.495f * w2;
            g_c2d[2 * t + 1] = 0.495f * w2;
        }
        return;
    }

    // ---- LSTM block (bid 128..135) ----
    {
        __shared__ float sPart[1024];
        __shared__ float s_x[128];
        __shared__ float s_gates[256];
        const int b = bid - 128;

        float4 wi[16];
        {
            const float4* pwi = (const float4*)(W_ih + t * 64);
            #pragma unroll
            for (int j = 0; j < 16; j++) wi[j] = pwi[j];
        }
        {
            int dq = t & 15, rc = t >> 4;
            const float* base = ope + (b * 258 + 1 + rc * 16) * 64 + dq * 4;
            float4 s = make_float4(0.f, 0.f, 0.f, 0.f);
            #pragma unroll
            for (int rr = 0; rr < 16; rr++) {
                float4 x = *(const float4*)(base + rr * 64);
                s.x += x.x; s.y += x.y; s.z += x.z; s.w += x.w;
            }
            *(float4*)(sPart + rc * 64 + dq * 4) = s;
        }
        if (t >= 64 && t < 128) s_x[t] = h_in[b * 64 + (t - 64)];
        __syncthreads();
        if (t < 64) {
            float s = 0.f;
            #pragma unroll
            for (int rc = 0; rc < 16; rc++) s += sPart[rc * 64 + t];
            s_x[t] = s * (1.0f / 256.0f);
        }
        __syncthreads();

        float acc = b_ih[t] + b_hh[t];
        #pragma unroll
        for (int j = 0; j < 16; j++) {
            float4 x4 = *(const float4*)(s_x + j * 4);
            acc += wi[j].x * x4.x + wi[j].y * x4.y + wi[j].z * x4.z + wi[j].w * x4.w;
        }
        {
            float4 wh[16];
            const float4* pwh = (const float4*)(W_hh + t * 64);
            #pragma unroll
            for (int j = 0; j < 16; j++) wh[j] = pwh[j];
            #pragma unroll
            for (int j = 0; j < 16; j++) {
                float4 x4 = *(const float4*)(s_x + 64 + j * 4);
                acc += wh[j].x * x4.x + wh[j].y * x4.y + wh[j].z * x4.z + wh[j].w * x4.w;
            }
        }
        s_gates[t] = acc;
        __syncthreads();

        if (t < 64) {
            float ig = sigm(s_gates[t]);
            float fg = sigm(s_gates[64 + t]);
            float gg = tanhf(s_gates[128 + t]);
            float og = sigm(s_gates[192 + t]);
            float cn = fg * c_in[b * 64 + t] + ig * gg;
            float hn = og * tanhf(cn);
            g_hn[b * 64 + t] = hn;
            out[OFF_HN + b * 64 + t] = hn;
            out[OFF_CN + b * 64 + t] = cn;
        }
    }
}

// ============================================================
// KB (consumer), 136 blocks x 512 thr, dsm 101376 B.
//  bid 0..127 : A tile. Phases:
//    A: stage sVd(dup raw vv), sW(raw w), consts, hn
//    B: u (tid<128) | Q=sum c1*w (tid 128..383, 4/i) | P'=sum c1*vv (tid 384.., 2/o)
//    C: sW += u (ALL 2048 float4s) ; U = sum c1*u (warp 0)
//    E: main f32x2 loop; pcb = U + ba2
//  bid 128..135: V per batch
// ============================================================
__global__ void __launch_bounds__(512) k_cons(
        const float* __restrict__ ba2p,
        const float* __restrict__ Wv0, const float* __restrict__ bv0,
        const float* __restrict__ Wv1, const float* __restrict__ bv1,
        const float* __restrict__ Wv2, const float* __restrict__ bv2,
        float* __restrict__ out)
{
    extern __shared__ float sm[];
    const int bid = blockIdx.x;
    const int tid = threadIdx.x;

    if (bid >= 128) {
        // ---- V block ----
        __shared__ float shn2[64], sz0[128], sz1[128];
        const int b = bid - 128;
        if (tid < 64) shn2[tid] = g_hn[b * 64 + tid];
        __syncthreads();
        if (tid < 128) {
            float acc = bv0[tid];
            const float4* row = (const float4*)(Wv0 + tid * 64);
            #pragma unroll
            for (int j = 0; j < 16; j++) {
                float4 w4 = row[j];
                float4 x4 = *(const float4*)(shn2 + 4 * j);
                acc += w4.x * x4.x + w4.y * x4.y + w4.z * x4.z + w4.w * x4.w;
            }
            sz0[tid] = acc;  // no activation on layer 0
        }
        __syncthreads();
        if (tid < 128) {
            float acc = bv1[tid];
            const float4* row = (const float4*)(Wv1 + tid * 128);
            #pragma unroll 8
            for (int j = 0; j < 32; j++) {
                float4 w4 = row[j];
                float4 x4 = *(const float4*)(sz0 + 4 * j);
                acc += w4.x * x4.x + w4.y * x4.y + w4.z * x4.z + w4.w * x4.w;
            }
            sz1[tid] = (acc >= 0.f) ? acc : 0.01f * acc;
        }
        __syncthreads();
        if (tid < 32) {
            float4 x = *(const float4*)(sz1 + tid * 4);
            float4 ww = *(const float4*)(Wv2 + tid * 4);
            float s = ww.x * x.x + ww.y * x.y + ww.z * x.z + ww.w * x.w;
            s = warp_sum(s);
            if (tid == 0) out[OFF_V + b] = s + bv2[0];
        }
        return;
    }

    // ---- A tile block (512 threads) ----
    float* sVd = sm;            // 16384
    float* sW  = sm + 16384;    // 8192
    float* sC2 = sm + 24576;    // 256
    float* sC1 = sm + 24832;    // 128
    float* sP  = sm + 24960;    // 64
    float* sQ  = sm + 25024;    // 64
    float* sU  = sm + 25088;    // 128
    float* shn = sm + 25216;    // 64
    float* sUc = sm + 25280;    // 4
    const int b = bid >> 4, oc = (bid >> 2) & 3, ic = bid & 3;

    const float* wsrc = g_wT  + b * 32768 + ic * 64;
    const float* vsrc = g_vvT + b * 32768 + oc * 64;

    // Phase A: stage sVd (dup raw vv), sW (raw w), constants, hn
    #pragma unroll
    for (int k = 0; k < 4; k++) {
        int l = tid + k * 512;
        int gg = l >> 4, q = (l & 15) << 2;
        float4 vv = *(const float4*)(vsrc + gg * 256 + q);
        float* vd = sVd + gg * 128 + q * 2;
        ((float4*)vd)[0] = make_float4(vv.x, vv.x, vv.y, vv.y);
        ((float4*)vd)[1] = make_float4(vv.z, vv.z, vv.w, vv.w);
        float4 wv = *(const float4*)(wsrc + gg * 256 + q);
        *(float4*)(sW + gg * 64 + q) = wv;
    }
    if (tid < 256) sC2[tid] = g_c2d[tid];
    else if (tid < 384) sC1[tid - 256] = g_c1[tid - 256];
    else if (tid < 448) shn[tid - 384] = g_hn[b * 64 + (tid - 384)];
    __syncthreads();

    // Phase B: u | Q | P'  (all concurrent)
    if (tid < 128) {
        float acc = g_bba[tid];
        const float4* row = (const float4*)(g_M2 + tid * 64);
        #pragma unroll
        for (int j = 0; j < 16; j++) {
            float4 w4 = row[j];
            float4 x4 = *(const float4*)(shn + 4 * j);
            acc += w4.x * x4.x + w4.y * x4.y + w4.z * x4.z + w4.w * x4.w;
        }
        sU[tid] = acc;
    } else if (tid < 384) {
        // Q[i] = sum_g c1[g]*w[g][i] ; 4 threads per i, 32 g each
        int idx = tid - 128;
        int i = idx >> 2, part = idx & 3;
        float s = 0.f;
        #pragma unroll 8
        for (int g = part * 32; g < part * 32 + 32; g++)
            s += sC1[g] * sW[g * 64 + i];
        s += __shfl_xor_sync(0xffffffffu, s, 1);
        s += __shfl_xor_sync(0xffffffffu, s, 2);
        if (part == 0) sQ[i] = s;
    } else {
        // P'[o] = sum_g c1[g]*vv[g][o] ; 2 threads per o, 64 g each
        int idx = tid - 384;
        int o = idx >> 1, half = idx & 1;
        float s = 0.f;
        #pragma unroll 8
        for (int g = half * 64; g < half * 64 + 64; g++)
            s += sC1[g] * sVd[g * 128 + 2 * o];
        s += __shfl_xor_sync(0xffffffffu, s, 1);
        if (half == 0) sP[o] = s;
    }
    __syncthreads();

    // Phase C: sW += u over ALL 2048 float4s ; U = sum c1*u (warp 0)
    #pragma unroll
    for (int k = 0; k < 4; k++) {
        int l = tid + k * 512;          // float4 index 0..2047
        float uu = sU[l >> 4];          // g-row = (l*4)/64 = l/16
        float4 w4 = *(float4*)(sW + l * 4);
        w4.x += uu; w4.y += uu; w4.z += uu; w4.w += uu;
        *(float4*)(sW + l * 4) = w4;
    }
    if (tid < 32) {
        float s = 0.f;
        #pragma unroll
        for (int j = 0; j < 4; j++)
            s += sC1[tid * 4 + j] * sU[tid * 4 + j];
        s = warp_sum(s);
        if (tid == 0) sUc[0] = s;
    }
    __syncthreads();

    // Phase E: main f32x2 loop, micro-tile 2o x 4i
    const int tx = tid & 15, ty = tid >> 4;
    unsigned long long a00 = 0, a01 = 0, a10 = 0, a11 = 0;
    const float* vbase = sVd + ty * 4;
    const float* wbase = sW + tx * 4;
    const unsigned long long* c2base = (const unsigned long long*)sC2;
    const unsigned long long MASK = 0x7FFFFFFF7FFFFFFFULL;

    #pragma unroll 8
    for (int gg = 0; gg < 128; gg++) {
        ulonglong2 vp = *(const ulonglong2*)(vbase + gg * 128);
        ulonglong2 wp = *(const ulonglong2*)(wbase + gg * 64);
        unsigned long long c2 = c2base[gg];
        unsigned long long tt;
        tt = addp(vp.x, wp.x) & MASK;  a00 = fmap(c2, tt, a00);
        tt = addp(vp.x, wp.y) & MASK;  a01 = fmap(c2, tt, a01);
        tt = addp(vp.y, wp.x) & MASK;  a10 = fmap(c2, tt, a10);
        tt = addp(vp.y, wp.y) & MASK;  a11 = fmap(c2, tt, a11);
    }

    const float pcb = sUc[0] + ba2p[0];
    float4 q4 = *(const float4*)(sQ + tx * 4);
    unsigned long long acc[2][2] = {{a00, a01}, {a10, a11}};
    #pragma unroll
    for (int r = 0; r < 2; r++) {
        float pr = sP[ty * 2 + r] + pcb;
        float4 res;
        res.x = plo(acc[r][0]) + pr + q4.x;
        res.y = phi(acc[r][0]) + pr + q4.y;
        res.z = plo(acc[r][1]) + pr + q4.z;
        res.w = phi(acc[r][1]) + pr + q4.w;
        int og = oc * 64 + ty * 2 + r;
        *(float4*)(out + OFF_A + b * 65536 + og * 256 + ic * 64 + tx * 4) = res;
    }
}

// ============================================================
extern "C" void kernel_launch(void* const* d_in, const int* in_sizes, int n_in,
                              void* d_out, int out_size)
{
    const float* ope   = (const float*)d_in[0];
    const float* ins   = (const float*)d_in[1];
    const float* h_in  = (const float*)d_in[2];
    const float* c_in  = (const float*)d_in[3];
    const float* W_ih  = (const float*)d_in[4];
    const float* W_hh  = (const float*)d_in[5];
    const float* b_ih  = (const float*)d_in[6];
    const float* b_hh  = (const float*)d_in[7];
    const float* Wv0   = (const float*)d_in[8];
    const float* bv0   = (const float*)d_in[9];
    const float* Wv1   = (const float*)d_in[10];
    const float* bv1   = (const float*)d_in[11];
    const float* Wv2   = (const float*)d_in[12];
    const float* bv2   = (const float*)d_in[13];
    const float* Wa0   = (const float*)d_in[14];
    const float* ba0   = (const float*)d_in[15];
    const float* Wa1   = (const float*)d_in[16];
    const float* ba1   = (const float*)d_in[17];
    const float* Wa2   = (const float*)d_in[18];
    const float* ba2   = (const float*)d_in[19];
    float* out = (float*)d_out;

    cudaFuncSetAttribute(k_prod, cudaFuncAttributeMaxDynamicSharedMemorySize, 69888);
    cudaFuncSetAttribute(k_cons, cudaFuncAttributeMaxDynamicSharedMemorySize, 101376);

    k_prod<<<145, 256, 69888>>>(ope, ins, h_in, c_in, W_ih, W_hh, b_ih, b_hh,
                                Wa0, ba0, Wa1, ba1, Wa2, out);
    k_cons<<<136, 512, 101376>>>(ba2, Wv0, bv0, Wv1, bv1, Wv2, bv2, out);
}